// round 4
// baseline (speedup 1.0000x reference)
#include <cuda_runtime.h>

// (B, D, H, W) = (2, 192, 192, 192) fp32
#define DD 192
#define HH 192
#define WW 192
#define PLANE 36864
#define VOL   7077888

#define TILE   32          // output tile in h and w
#define DCHUNK 48          // d-extent per block
#define NT     512
#define SWSTR  35          // padded stride (conflict-free for W-stage stores)

#define INV_VOL (1.0f / 729.0f)
#define EPS 1e-5f

// Fully fused 9^3 LNCC. Per d-slice:
//   W-stage: 320 threads load 12-value windows (3 aligned float4 per field)
//            directly from gmem, compute 4 sliding W-sums each, store to s_w.
//   H-stage: 512 threads read 10 rows of W-sums -> 2 HW-sums each.
//   D-stage: 8-deep register ring per output + fused epilogue.
__global__ void __launch_bounds__(NT, 1)
lncc_fused2(const float* __restrict__ gt,
            const float* __restrict__ gp,
            float* __restrict__ out)
{
    __shared__ float2 s01[2][40][SWSTR];   // (sum_t, sum_p)   22.4 KB
    __shared__ float  s2 [2][40][SWSTR];   // sum_tp           11.2 KB

    const int tid = threadIdx.x;
    const int bx  = blockIdx.x;
    const int wt  = bx % 6;
    const int ht  = (bx / 6) % 6;
    const int dc  = (bx / 36) % 4;
    const int b   = bx / 144;
    const int w0 = wt * TILE, h0 = ht * TILE, d0 = dc * DCHUNK;

    // ---- W-stage thread geometry: 40 rows x 8 segments of 4 outputs ----
    const bool wact = tid < 320;
    const int wr   = tid >> 3;            // 0..39
    const int wseg = tid & 7;             // 0..7
    const int gh   = h0 - 4 + wr;
    const int gw0  = w0 + wseg * 4 - 4;   // multiple of 4 -> float4 aligned
    const bool hok = wact && (unsigned)gh < HH;
    const int rowbase = b * VOL + gh * WW;
    bool cok[3];
#pragma unroll
    for (int c = 0; c < 3; ++c)
        cok[c] = hok && (gw0 + c * 4 >= 0) && (gw0 + c * 4 < WW);

    float4 Pt[3], Pp[3];

    auto prefetch = [&](int dz) {
        const bool dok = (unsigned)dz < DD;
        const int base = rowbase + dz * PLANE + gw0;
#pragma unroll
        for (int c = 0; c < 3; ++c) {
            if (dok && cok[c]) {
                Pt[c] = *(const float4*)(gt + base + c * 4);
                Pp[c] = *(const float4*)(gp + base + c * 4);
            } else {
                Pt[c] = make_float4(0.f, 0.f, 0.f, 0.f);
                Pp[c] = make_float4(0.f, 0.f, 0.f, 0.f);
            }
        }
    };

    auto wstore = [&](int bsel) {
        if (!wact) return;
        const float t[12] = {Pt[0].x, Pt[0].y, Pt[0].z, Pt[0].w,
                             Pt[1].x, Pt[1].y, Pt[1].z, Pt[1].w,
                             Pt[2].x, Pt[2].y, Pt[2].z, Pt[2].w};
        const float p[12] = {Pp[0].x, Pp[0].y, Pp[0].z, Pp[0].w,
                             Pp[1].x, Pp[1].y, Pp[1].z, Pp[1].w,
                             Pp[2].x, Pp[2].y, Pp[2].z, Pp[2].w};
        float m[12];
#pragma unroll
        for (int k = 0; k < 12; ++k) m[k] = t[k] * p[k];

        float st = 0.f, sp = 0.f, stp = 0.f;
#pragma unroll
        for (int k = 0; k < 9; ++k) { st += t[k]; sp += p[k]; stp += m[k]; }
        const int ow = wseg * 4;
        s01[bsel][wr][ow] = make_float2(st, sp);
        s2 [bsel][wr][ow] = stp;
#pragma unroll
        for (int q = 1; q < 4; ++q) {
            st  += t[8 + q] - t[q - 1];
            sp  += p[8 + q] - p[q - 1];
            stp += m[8 + q] - m[q - 1];
            s01[bsel][wr][ow + q] = make_float2(st, sp);
            s2 [bsel][wr][ow + q] = stp;
        }
    };

    // ---- H-stage geometry: 2 consecutive h-outputs per thread ----
    const int ty = tid >> 5;
    const int tx = tid & 31;
    const int rb = ty << 1;

    auto h_stage = [&](int bsel,
                       float& a0, float& a1, float& a2,
                       float& b0, float& b1, float& b2) {
        const float2 v0  = s01[bsel][rb][tx];
        const float  w0v = s2 [bsel][rb][tx];
        a0 = v0.x; a1 = v0.y; a2 = w0v;
#pragma unroll
        for (int k = 1; k < 9; ++k) {
            const float2 v = s01[bsel][rb + k][tx];
            a0 += v.x; a1 += v.y; a2 += s2[bsel][rb + k][tx];
        }
        const float2 v9  = s01[bsel][rb + 9][tx];
        const float  w9v = s2 [bsel][rb + 9][tx];
        b0 = a0 - v0.x + v9.x;
        b1 = a1 - v0.y + v9.y;
        b2 = a2 - w0v + w9v;
    };

    // ---- D ring: 8 deep x 3 fields x 2 outputs ----
    float r0a[8], r1a[8], r2a[8], r0b[8], r1b[8], r2b[8];
#pragma unroll
    for (int i = 0; i < 8; ++i) {
        r0a[i] = r1a[i] = r2a[i] = 0.f;
        r0b[i] = r1b[i] = r2b[i] = 0.f;
    }
    float s0a = 0.f, s1a = 0.f, s2a = 0.f;
    float s0b = 0.f, s1b = 0.f, s2b = 0.f;

    int buf = 0;
    prefetch(d0 - 4);

    // ---- warmup: ingest slices d0-4 .. d0+3 ----
#pragma unroll
    for (int i = 0; i < 8; ++i) {
        wstore(buf);
        prefetch(d0 - 3 + i);
        __syncthreads();
        float a0, a1, a2, b0, b1, b2;
        h_stage(buf, a0, a1, a2, b0, b1, b2);
        r0a[i] = a0; r1a[i] = a1; r2a[i] = a2;
        r0b[i] = b0; r1b[i] = b1; r2b[i] = b2;
        s0a += a0; s1a += a1; s2a += a2;
        s0b += b0; s1b += b1; s2b += b2;
        buf ^= 1;
    }

    // ---- main loop: outputs d0 .. d0+47 ----
    const int ob = b * VOL + (h0 + rb) * WW + w0 + tx;
    for (int s8 = 0; s8 < DCHUNK / 8; ++s8) {
#pragma unroll
        for (int ph = 0; ph < 8; ++ph) {
            const int step = s8 * 8 + ph;
            wstore(buf);                  // slice d0+4+step
            prefetch(d0 + 5 + step);
            __syncthreads();
            float a0, a1, a2, b0, b1, b2;
            h_stage(buf, a0, a1, a2, b0, b1, b2);
            s0a += a0; s1a += a1; s2a += a2;
            s0b += b0; s1b += b1; s2b += b2;

            const float ca = s2a - s1a * s0a * INV_VOL;
            const float cb = s2b - s1b * s0b * INV_VOL;
            const int o = ob + (d0 + step) * PLANE;
            out[o]      = fmaf(ca, ca, EPS);
            out[o + WW] = fmaf(cb, cb, EPS);

            s0a -= r0a[ph]; r0a[ph] = a0;
            s1a -= r1a[ph]; r1a[ph] = a1;
            s2a -= r2a[ph]; r2a[ph] = a2;
            s0b -= r0b[ph]; r0b[ph] = b0;
            s1b -= r1b[ph]; r1b[ph] = b1;
            s2b -= r2b[ph]; r2b[ph] = b2;
            buf ^= 1;
        }
    }
}

extern "C" void kernel_launch(void* const* d_in, const int* in_sizes, int n_in,
                              void* d_out, int out_size) {
    const float* y_true = (const float*)d_in[0];
    const float* y_pred = (const float*)d_in[1];
    float* out = (float*)d_out;

    // 6 w-tiles x 6 h-tiles x 4 d-chunks x 2 batches = 288 blocks
    lncc_fused2<<<288, NT>>>(y_true, y_pred, out);
}